// round 8
// baseline (speedup 1.0000x reference)
#include <cuda_runtime.h>
#include <cuda_fp16.h>
#include <cstdint>

// ---------------------------------------------------------------------------
// ConstrainedEnhancementModel on GB300 (ptxas target sm_103: no 'a' features).
// R8: gemm6 uses fp16-ACCUMULATE mma.sync (m16n8k16 f16.f16.f16.f16) with
// chunked f32 correction every 16 k-tiles. 512-thread CTA, 16 warps of 32x32
// tiles, 8-stage cp.async pipeline (prefetch distance 7).
// ---------------------------------------------------------------------------

#define NB   512
#define NL   256
#define NF   32
#define NH   4096
#define NOUTCOL (NH * NF)          // 131072
#define LAST_KNOT ((NL - 1) * 16)  // 4080

__device__ float  g_h1[512 * 1024];
__device__ float  g_h2[512 * 512];
__device__ float  g_fe[512 * 256];
__device__ float  g_d1[512 * 512];
__device__ __half g_d2h[512 * 1024];                // tiled [kt][m][16]
__device__ __half g_w6t[(size_t)NOUTCOL * 1024];    // tiled [nblk][kt][128][16]

// ===========================================================================
// helpers
// ===========================================================================
__device__ __forceinline__ uint32_t smem_u32(const void* p) {
    uint32_t a;
    asm("{ .reg .u64 t; cvta.to.shared.u64 t, %1; cvt.u32.u64 %0, t; }"
        : "=r"(a) : "l"(p));
    return a;
}
__device__ __forceinline__ void cp16_cg(uint32_t dst, const void* src) {
    asm volatile("cp.async.cg.shared.global [%0], [%1], 16;"
                 :: "r"(dst), "l"(src) : "memory");
}
#define CP_COMMIT() asm volatile("cp.async.commit_group;" ::: "memory")
#define CP_WAIT6()  asm volatile("cp.async.wait_group 6;" ::: "memory")

__device__ __forceinline__ void ldsm_x4(uint32_t& r0, uint32_t& r1,
                                        uint32_t& r2, uint32_t& r3, uint32_t addr) {
    asm volatile("ldmatrix.sync.aligned.m8n8.x4.shared.b16 {%0,%1,%2,%3}, [%4];"
                 : "=r"(r0), "=r"(r1), "=r"(r2), "=r"(r3) : "r"(addr));
}

// fp16-accumulate MMA: {c0,c1} are packed half2 (rows g and g+8)
__device__ __forceinline__ void mma_f16acc(uint32_t& c0, uint32_t& c1,
                                           uint32_t a0, uint32_t a1,
                                           uint32_t a2, uint32_t a3,
                                           uint32_t b0, uint32_t b1) {
    asm volatile(
        "mma.sync.aligned.m16n8k16.row.col.f16.f16.f16.f16 "
        "{%0,%1}, {%2,%3,%4,%5}, {%6,%7}, {%0,%1};"
        : "+r"(c0), "+r"(c1)
        : "r"(a0), "r"(a1), "r"(a2), "r"(a3), "r"(b0), "r"(b1));
}

// ===========================================================================
// Combined L1 + pack_w6 kernel (heterogeneous 1D grid) — unchanged from R7.
// ===========================================================================
__global__ void __launch_bounds__(256)
l1_and_pack(const float* __restrict__ low, const float* __restrict__ w1,
            const float* __restrict__ b1, float* __restrict__ h1,
            const float* __restrict__ w6, __half* __restrict__ w6t)
{
    const int bx  = blockIdx.x;
    const int tid = threadIdx.x;

    if (bx < 128) {
        constexpr int BM = 64, BN = 64, BK = 16, TM = 4, TN = 4;
        constexpr int THREADS = 256;
        const int N = 1024, K = 8192;
        __shared__ float As[BK][BM + 4];
        __shared__ float Bs[BK][BN];

        const int bn = (bx & 15) * BN;
        const int bm = (bx >> 4) * BM;
        const int tx = tid % (BN / TN);
        const int ty = tid / (BN / TN);

        float acc[TM][TN];
#pragma unroll
        for (int i = 0; i < TM; i++)
#pragma unroll
            for (int j = 0; j < TN; j++) acc[i][j] = 0.0f;

        constexpr int AV = BK / 4, AT = BM * AV;
        constexpr int BV = BN / 4, BT = BK * BV;

        for (int k0 = 0; k0 < K; k0 += BK) {
            for (int i = tid; i < AT; i += THREADS) {
                int r = i / AV, c4 = (i % AV) * 4;
                float4 v = *reinterpret_cast<const float4*>(
                    low + (size_t)(bm + r) * K + k0 + c4);
                As[c4 + 0][r] = v.x; As[c4 + 1][r] = v.y;
                As[c4 + 2][r] = v.z; As[c4 + 3][r] = v.w;
            }
            for (int i = tid; i < BT; i += THREADS) {
                int r = i / BV, c4 = (i % BV) * 4;
                *reinterpret_cast<float4*>(&Bs[r][c4]) =
                    *reinterpret_cast<const float4*>(
                        w1 + (size_t)(k0 + r) * N + bn + c4);
            }
            __syncthreads();
#pragma unroll
            for (int kk = 0; kk < BK; kk++) {
                float ra[TM], rb[TN];
#pragma unroll
                for (int i = 0; i < TM; i += 4)
                    *reinterpret_cast<float4*>(&ra[i]) =
                        *reinterpret_cast<const float4*>(&As[kk][ty * TM + i]);
#pragma unroll
                for (int j = 0; j < TN; j += 4)
                    *reinterpret_cast<float4*>(&rb[j]) =
                        *reinterpret_cast<const float4*>(&Bs[kk][tx * TN + j]);
#pragma unroll
                for (int i = 0; i < TM; i++)
#pragma unroll
                    for (int j = 0; j < TN; j++)
                        acc[i][j] = fmaf(ra[i], rb[j], acc[i][j]);
            }
            __syncthreads();
        }
#pragma unroll
        for (int i = 0; i < TM; i++) {
            int row = bm + ty * TM + i;
#pragma unroll
            for (int j = 0; j < TN; j += 4) {
                int col = bn + tx * TN + j;
                float4 v;
                v.x = fmaxf(acc[i][j + 0] + b1[col + 0], 0.0f);
                v.y = fmaxf(acc[i][j + 1] + b1[col + 1], 0.0f);
                v.z = fmaxf(acc[i][j + 2] + b1[col + 2], 0.0f);
                v.w = fmaxf(acc[i][j + 3] + b1[col + 3], 0.0f);
                *reinterpret_cast<float4*>(h1 + (size_t)row * N + col) = v;
            }
        }
    } else {
        __shared__ __half ts[16][136];
        const int pid = bx - 128;
        const int blk = pid >> 6;
        const int kt  = pid & 63;

#pragma unroll
        for (int i = tid; i < 2048; i += 256) {
            const int k = i >> 7, n = i & 127;
            ts[k][n] = __float2half(
                w6[(size_t)(kt * 16 + k) * NOUTCOL + blk * 128 + n]);
        }
        __syncthreads();

        const int n  = tid >> 1;
        const int kh = (tid & 1) * 8;
        __half tmp[8];
#pragma unroll
        for (int j = 0; j < 8; j++) tmp[j] = ts[kh + j][n];
        __half* dst = w6t + ((size_t)(blk * 64 + kt) * 128 + n) * 16 + kh;
        *reinterpret_cast<uint4*>(dst) = *reinterpret_cast<const uint4*>(tmp);
    }
}

// ===========================================================================
// GEMM6 fp16-accum: out = epilogue( d2h @ w6t^T + b6 )
// CTA 128x128, 512 threads, 16 warps (4M x 4N), warp tile 32x32, K-step 16.
// 8-stage cp.async (dist 7). f16 accumulators dumped to f32 every 16 kt.
// ===========================================================================
#define G6_STG    8
#define G6_PITCH  24                       // halfs per row (16 data + 8 pad)
#define G6_TILEH  (128 * G6_PITCH)         // 3072 halfs per stage
#define G6_TILEB  (G6_TILEH * 2)           // 6144 bytes per stage
#define G6_NKT    64
#define G6_SMEMB  (2 * G6_STG * G6_TILEB + 512)

__global__ void __launch_bounds__(512, 1)
gemm6_fp16(const __half* __restrict__ Ah,   // d2h tiled [64][512][16]
           const __half* __restrict__ Bt,   // w6t tiled [1024][64][128][16]
           const float* __restrict__ bias,
           const float* __restrict__ low,
           float* __restrict__ out)
{
    extern __shared__ __half sm[];
    __half* Asm = sm;
    __half* Bsm = sm + G6_STG * G6_TILEH;
    float*  sbias = reinterpret_cast<float*>(sm + 2 * G6_STG * G6_TILEH);

    const int tid  = threadIdx.x;
    const int wid  = tid >> 5;      // 0..15
    const int lane = tid & 31;
    const int g    = lane >> 2;
    const int q    = lane & 3;

    const int bm = blockIdx.x * 128;
    const int bn = blockIdx.y * 128;

    const int wm = (wid >> 2) * 32;    // 0..96
    const int wn = (wid & 3) * 32;     // 0..96

    if (tid < 128) sbias[tid] = bias[bn + tid];

    const uint32_t aBase = smem_u32(Asm);
    const uint32_t bBase = smem_u32(Bsm);

    // cp.async: 512 threads, each owns ONE 16B chunk of one operand per stage
    const bool isA = (tid < 256);
    const int  ci  = isA ? tid : (tid - 256);
    const __half* src0 = isA
        ? (Ah + (size_t)bm * 16 + ci * 8)
        : (Bt + (size_t)blockIdx.y * 64 * 2048 + ci * 8);
    const int stepK = isA ? 8192 : 2048;
    const uint32_t dst0 = (isA ? aBase : bBase) + (ci >> 1) * 48 + (ci & 1) * 16;

#define G6_LOAD(s, kt) cp16_cg(dst0 + (s) * G6_TILEB, src0 + (size_t)(kt) * stepK)

    G6_LOAD(0, 0); CP_COMMIT();
    G6_LOAD(1, 1); CP_COMMIT();
    G6_LOAD(2, 2); CP_COMMIT();
    G6_LOAD(3, 3); CP_COMMIT();
    G6_LOAD(4, 4); CP_COMMIT();
    G6_LOAD(5, 5); CP_COMMIT();
    G6_LOAD(6, 6); CP_COMMIT();

    // ldmatrix base addresses (slot mapping validated R5-R7)
    const int mi = lane >> 3;
    const int r8 = lane & 7;
    const uint32_t aLd = aBase +
        (uint32_t)(((wm + (mi & 1) * 8 + r8) * G6_PITCH + (mi >> 1) * 8) * 2);
    const uint32_t bLd = bBase +
        (uint32_t)(((wn + (mi >> 1) * 8 + r8) * G6_PITCH + (mi & 1) * 8) * 2);

    uint32_t acch[2][4][2];            // f16 packed accumulators
    float    acc[2][4][4];             // f32 master accumulators
#pragma unroll
    for (int i = 0; i < 2; i++)
#pragma unroll
        for (int j = 0; j < 4; j++) {
            acch[i][j][0] = acch[i][j][1] = 0u;
#pragma unroll
            for (int k = 0; k < 4; k++) acc[i][j][k] = 0.0f;
        }

    int s = 0, sl = 7;
    for (int kt = 0; kt < G6_NKT; kt++) {
        CP_WAIT6();
        __syncthreads();
        if (kt + 7 < G6_NKT) {
            G6_LOAD(sl, kt + 7);
        }
        CP_COMMIT();

        const uint32_t so = (uint32_t)s * G6_TILEB;

        uint32_t bf[4][2];
#pragma unroll
        for (int p = 0; p < 2; p++)
            ldsm_x4(bf[2 * p][0], bf[2 * p][1],
                    bf[2 * p + 1][0], bf[2 * p + 1][1],
                    bLd + p * (16 * G6_PITCH * 2) + so);

#pragma unroll
        for (int mt = 0; mt < 2; mt++) {
            uint32_t a0, a1, a2, a3;
            ldsm_x4(a0, a1, a2, a3, aLd + mt * (16 * G6_PITCH * 2) + so);
#pragma unroll
            for (int nt = 0; nt < 4; nt++)
                mma_f16acc(acch[mt][nt][0], acch[mt][nt][1],
                           a0, a1, a2, a3, bf[nt][0], bf[nt][1]);
        }

        // chunk dump: fold f16 accs into f32 every 16 kt
        if ((kt & 15) == 15) {
#pragma unroll
            for (int mt = 0; mt < 2; mt++)
#pragma unroll
                for (int nt = 0; nt < 4; nt++) {
                    float2 lo = __half22float2(
                        *reinterpret_cast<const __half2*>(&acch[mt][nt][0]));
                    float2 hi = __half22float2(
                        *reinterpret_cast<const __half2*>(&acch[mt][nt][1]));
                    acc[mt][nt][0] += lo.x;  acc[mt][nt][1] += lo.y;
                    acc[mt][nt][2] += hi.x;  acc[mt][nt][3] += hi.y;
                    acch[mt][nt][0] = 0u;    acch[mt][nt][1] = 0u;
                }
        }

        s  = (s + 1) & (G6_STG - 1);
        sl = (sl + 1) & (G6_STG - 1);
    }

    // ---- fused epilogue (warp-uniform t: wn spans exactly one t) ----
    const int t   = (bn + wn) >> 5;
    const int rem = t & 15;
    const int seg = t >> 4;
    const bool knot  = (rem == 0);
    const bool inseg = (!knot) && (t < LAST_KNOT);
    const float alpha = (float)rem * 0.0625f;
    const int segB = (seg < NL - 1) ? seg + 1 : NL - 1;

#pragma unroll
    for (int mt = 0; mt < 2; mt++) {
#pragma unroll
        for (int h = 0; h < 2; h++) {
            const int r = bm + wm + mt * 16 + g + h * 8;
            const float* lowr = low + (size_t)r * (NL * NF);
            float* outr = out + (size_t)r * NOUTCOL + bn + wn;
#pragma unroll
            for (int nt = 0; nt < 4; nt++) {
                const int f = nt * 8 + 2 * q;
                float dec0 = acc[mt][nt][2 * h]     + sbias[wn + f];
                float dec1 = acc[mt][nt][2 * h + 1] + sbias[wn + f + 1];
                float2 la = *reinterpret_cast<const float2*>(lowr + seg  * NF + f);
                float2 lb = *reinterpret_cast<const float2*>(lowr + segB * NF + f);
                float lin0 = (1.0f - alpha) * la.x + alpha * lb.x;
                float lin1 = (1.0f - alpha) * la.y + alpha * lb.y;
                float r0 = knot ? la.x : (inseg ? 0.8f * lin0 + 0.2f * dec0 : dec0);
                float r1 = knot ? la.y : (inseg ? 0.8f * lin1 + 0.2f * dec1 : dec1);
                *reinterpret_cast<float2*>(outr + f) = make_float2(r0, r1);
            }
        }
    }
#undef G6_LOAD
}

// ===========================================================================
// Small-layer SIMT SGEMM (unchanged); TILEDH stores fp16 tiled [col/16][row][16]
// ===========================================================================
template <int BM, int BN, int BK, int TM, int TN, bool RELU, bool TILEDH>
__global__ __launch_bounds__((BM / TM) * (BN / TN))
void sgemm_bias(const float* __restrict__ A, const float* __restrict__ Bm,
                const float* __restrict__ bias, void* __restrict__ Cv,
                int M, int N, int K)
{
    constexpr int THREADS = (BM / TM) * (BN / TN);
    __shared__ float As[BK][BM + 4];
    __shared__ float Bs[BK][BN];

    const int tid = threadIdx.x;
    const int bn  = blockIdx.x * BN;
    const int bm  = blockIdx.y * BM;
    const int tx  = tid % (BN / TN);
    const int ty  = tid / (BN / TN);

    float acc[TM][TN];
#pragma unroll
    for (int i = 0; i < TM; i++)
#pragma unroll
        for (int j = 0; j < TN; j++) acc[i][j] = 0.0f;

    constexpr int AV = BK / 4, AT = BM * AV;
    constexpr int BV = BN / 4, BT = BK * BV;

    for (int k0 = 0; k0 < K; k0 += BK) {
        for (int i = tid; i < AT; i += THREADS) {
            int r = i / AV, c4 = (i % AV) * 4;
            float4 v = *reinterpret_cast<const float4*>(
                A + (size_t)(bm + r) * K + k0 + c4);
            As[c4 + 0][r] = v.x; As[c4 + 1][r] = v.y;
            As[c4 + 2][r] = v.z; As[c4 + 3][r] = v.w;
        }
        for (int i = tid; i < BT; i += THREADS) {
            int r = i / BV, c4 = (i % BV) * 4;
            *reinterpret_cast<float4*>(&Bs[r][c4]) =
                *reinterpret_cast<const float4*>(
                    Bm + (size_t)(k0 + r) * N + bn + c4);
        }
        __syncthreads();

#pragma unroll
        for (int kk = 0; kk < BK; kk++) {
            float ra[TM], rb[TN];
#pragma unroll
            for (int i = 0; i < TM; i += 4)
                *reinterpret_cast<float4*>(&ra[i]) =
                    *reinterpret_cast<const float4*>(&As[kk][ty * TM + i]);
#pragma unroll
            for (int j = 0; j < TN; j += 4)
                *reinterpret_cast<float4*>(&rb[j]) =
                    *reinterpret_cast<const float4*>(&Bs[kk][tx * TN + j]);
#pragma unroll
            for (int i = 0; i < TM; i++)
#pragma unroll
                for (int j = 0; j < TN; j++)
                    acc[i][j] = fmaf(ra[i], rb[j], acc[i][j]);
        }
        __syncthreads();
    }

#pragma unroll
    for (int i = 0; i < TM; i++) {
        int row = bm + ty * TM + i;
#pragma unroll
        for (int j = 0; j < TN; j += 4) {
            int col = bn + tx * TN + j;
            float4 v;
            v.x = acc[i][j + 0] + bias[col + 0];
            v.y = acc[i][j + 1] + bias[col + 1];
            v.z = acc[i][j + 2] + bias[col + 2];
            v.w = acc[i][j + 3] + bias[col + 3];
            if (RELU) {
                v.x = fmaxf(v.x, 0.0f);
                v.y = fmaxf(v.y, 0.0f);
                v.z = fmaxf(v.z, 0.0f);
                v.w = fmaxf(v.w, 0.0f);
            }
            if (TILEDH) {
                __half* C = (__half*)Cv;
                __half* p = C + ((size_t)(col >> 4) * M + row) * 16 + (col & 15);
                __half2 h0 = __floats2half2_rn(v.x, v.y);
                __half2 h1 = __floats2half2_rn(v.z, v.w);
                *reinterpret_cast<__half2*>(p)     = h0;
                *reinterpret_cast<__half2*>(p + 2) = h1;
            } else {
                float* C = (float*)Cv;
                *reinterpret_cast<float4*>(C + (size_t)row * N + col) = v;
            }
        }
    }
}

// ---------------------------------------------------------------------------
extern "C" void kernel_launch(void* const* d_in, const int* in_sizes, int n_in,
                              void* d_out, int out_size)
{
    const float* low = (const float*)d_in[0];
    const float* w1  = (const float*)d_in[1];
    const float* b1  = (const float*)d_in[2];
    const float* w2  = (const float*)d_in[3];
    const float* b2  = (const float*)d_in[4];
    const float* w3  = (const float*)d_in[5];
    const float* b3  = (const float*)d_in[6];
    const float* w4  = (const float*)d_in[7];
    const float* b4  = (const float*)d_in[8];
    const float* w5  = (const float*)d_in[9];
    const float* b5  = (const float*)d_in[10];
    const float* w6  = (const float*)d_in[11];
    const float* b6  = (const float*)d_in[12];
    float* out = (float*)d_out;

    float  *h1, *h2, *fe, *d1;
    __half *d2h, *w6t;
    cudaGetSymbolAddress((void**)&h1,  g_h1);
    cudaGetSymbolAddress((void**)&h2,  g_h2);
    cudaGetSymbolAddress((void**)&fe,  g_fe);
    cudaGetSymbolAddress((void**)&d1,  g_d1);
    cudaGetSymbolAddress((void**)&d2h, g_d2h);
    cudaGetSymbolAddress((void**)&w6t, g_w6t);

    cudaFuncSetAttribute(gemm6_fp16,
                         cudaFuncAttributeMaxDynamicSharedMemorySize, G6_SMEMB);

    // Launch 1: L1 + pack_w6
    l1_and_pack<<<128 + 1024 * 64, 256>>>(low, w1, b1, h1, w6, w6t);
    // Launch 2-5: L2..L5
    sgemm_bias<64, 64, 16, 4, 4, true, false>
        <<<dim3(512 / 64, 512 / 64), 256>>>(h1, w2, b2, h2, 512, 512, 1024);
    sgemm_bias<64, 64, 16, 4, 4, false, false>
        <<<dim3(256 / 64, 512 / 64), 256>>>(h2, w3, b3, fe, 512, 256, 512);
    sgemm_bias<64, 64, 16, 4, 4, true, false>
        <<<dim3(512 / 64, 512 / 64), 256>>>(fe, w4, b4, d1, 512, 512, 256);
    sgemm_bias<64, 64, 16, 4, 4, true, true>
        <<<dim3(1024 / 64, 512 / 64), 256>>>(d1, w5, b5, d2h, 512, 1024, 512);
    // Launch 6: GEMM6 fp16-accum
    gemm6_fp16<<<dim3(4, NOUTCOL / 128), 512, G6_SMEMB>>>(d2h, w6t, b6, low, out);
}